// round 8
// baseline (speedup 1.0000x reference)
#include <cuda_runtime.h>
#include <math.h>

#define NPTS 8192
#define HID 128
#define WARPS_PER_BLOCK 18
#define NTHREADS (WARPS_PER_BLOCK * 32)   // 576 -> 112-reg cap
#define NBLOCKS 148
#define NWG (NBLOCKS * WARPS_PER_BLOCK)
#define WT_PITCH 132     // 128 + 4 pad -> conflict-free strided LDS.128

#define MU   80.77f
#define LAM  121.15f
#define GC   2.7e-3f
#define LEN  0.015f

typedef unsigned long long u64;

// Per-warp partial sums (deterministic slots, no atomics on data)
__device__ double g_part[NWG][3];
__device__ int g_count = 0;   // self-resetting: returns to 0 after every launch

// Shared memory layout (floats):
//   [0, 128*132)              W1T  (transposed, padded)
//   [128*132, 2*128*132)      W2T
//   [2*128*132, +18*7*128)    per-warp jet state
#define SMEM_FLOATS (2 * HID * WT_PITCH + WARPS_PER_BLOCK * 7 * HID)
#define SMEM_BYTES  (SMEM_FLOATS * 4)

__device__ __forceinline__ u64 ffma2(u64 a, u64 b, u64 c)
{
    u64 d;
    asm("fma.rn.f32x2 %0, %1, %2, %3;" : "=l"(d) : "l"(a), "l"(b), "l"(c));
    return d;
}
__device__ __forceinline__ float pair_sum(u64 v)
{
    return __uint_as_float((unsigned)(v & 0xffffffffu)) +
           __uint_as_float((unsigned)(v >> 32));
}

// activation jet update for one output unit j, given pre-activation jet af[7]
__device__ __forceinline__ void write_act(float* __restrict__ S,
                                          const float* __restrict__ af,
                                          float bj, int j)
{
    float zv = af[0] + bj;
    float T  = tanhf(zv);
    float Sx = 1.f - T * T;
    float c2 = -2.f * T * Sx;
    float z1 = af[1], z2 = af[2], zt = af[3];
    S[0 * HID + j] = T;
    S[1 * HID + j] = Sx * z1;
    S[2 * HID + j] = Sx * z2;
    S[3 * HID + j] = Sx * zt;
    S[4 * HID + j] = fmaf(c2 * z1, z1, Sx * af[4]);
    S[5 * HID + j] = fmaf(c2 * z1, z2, Sx * af[5]);
    S[6 * HID + j] = fmaf(c2 * z2, z2, Sx * af[6]);
}

__device__ __forceinline__ void hidden_layer(float* __restrict__ S,
                                             const float* __restrict__ WT,
                                             const float* __restrict__ b,
                                             int lane)
{
    // acc[u][c]: packed float2 partial sums (even-i / odd-i lanes of K)
    u64 acc[4][7];
#pragma unroll
    for (int u = 0; u < 4; u++)
#pragma unroll
        for (int c = 0; c < 7; c++) acc[u][c] = 0ull;

    const float* w0p = WT + lane * WT_PITCH;

#pragma unroll 2
    for (int i0 = 0; i0 < HID; i0 += 4) {
        // 4 strided weight vectors (one per output unit), read ONCE per chunk
        ulonglong2 wv[4];
#pragma unroll
        for (int u = 0; u < 4; u++)
            wv[u] = *reinterpret_cast<const ulonglong2*>(w0p + u * (32 * WT_PITCH) + i0);
        // channel-inner: one broadcast jet read, 8 packed FMAs
#pragma unroll
        for (int c = 0; c < 7; c++) {
            const ulonglong2 sv = *reinterpret_cast<const ulonglong2*>(S + c * HID + i0);
            acc[0][c] = ffma2(sv.x, wv[0].x, acc[0][c]);
            acc[0][c] = ffma2(sv.y, wv[0].y, acc[0][c]);
            acc[1][c] = ffma2(sv.x, wv[1].x, acc[1][c]);
            acc[1][c] = ffma2(sv.y, wv[1].y, acc[1][c]);
            acc[2][c] = ffma2(sv.x, wv[2].x, acc[2][c]);
            acc[2][c] = ffma2(sv.y, wv[2].y, acc[2][c]);
            acc[3][c] = ffma2(sv.x, wv[3].x, acc[3][c]);
            acc[3][c] = ffma2(sv.y, wv[3].y, acc[3][c]);
        }
    }

    __syncwarp();   // everyone done READING S before we overwrite it
#pragma unroll
    for (int u = 0; u < 4; u++) {
        int j = lane + 32 * u;
        float af[7];
#pragma unroll
        for (int c = 0; c < 7; c++) af[c] = pair_sum(acc[u][c]);
        write_act(S, af, b[j], j);
    }
    __syncwarp();   // writes visible before next layer reads
}

__global__ __launch_bounds__(NTHREADS, 1)
void pinn_kernel(const float* __restrict__ x,  const float* __restrict__ t,
                 const float* __restrict__ W0, const float* __restrict__ b0,
                 const float* __restrict__ W1, const float* __restrict__ b1,
                 const float* __restrict__ W2, const float* __restrict__ b2,
                 const float* __restrict__ W3, const float* __restrict__ b3,
                 float* __restrict__ out)
{
    extern __shared__ float smem[];
    float* W1T = smem;
    float* W2T = smem + HID * WT_PITCH;
    float* ST  = smem + 2 * HID * WT_PITCH;

    const int tid = threadIdx.x;
    // cooperative load + transpose of the two hidden weight matrices
    for (int idx = tid; idx < HID * HID; idx += NTHREADS) {
        int i = idx >> 7;      // input index (row of W)
        int j = idx & 127;     // output index (col of W)
        W1T[j * WT_PITCH + i] = W1[idx];
        W2T[j * WT_PITCH + i] = W2[idx];
    }
    __syncthreads();

    const int warp = tid >> 5;
    const int lane = tid & 31;
    float* S = ST + warp * 7 * HID;

    double a0 = 0.0, a1 = 0.0, a2 = 0.0;

    // balanced point range for this block; warp-strided within block
    const int pstart = (blockIdx.x * NPTS) / NBLOCKS;
    const int pend   = ((blockIdx.x + 1) * NPTS) / NBLOCKS;

    for (int p = pstart + warp; p < pend; p += WARPS_PER_BLOCK) {
        const float x1 = x[2 * p], x2 = x[2 * p + 1], tt = t[p];

        // ---- layer 0 (3 -> 128) + tanh: jet seeded analytically ----
#pragma unroll
        for (int u = 0; u < 4; u++) {
            int j = lane + 32 * u;
            float w0 = W0[j], w1 = W0[HID + j], w2 = W0[2 * HID + j];
            float zv = fmaf(tt, w2, fmaf(x2, w1, fmaf(x1, w0, b0[j])));
            float T  = tanhf(zv);
            float Sx = 1.f - T * T;
            float c2 = -2.f * T * Sx;
            S[0 * HID + j] = T;
            S[1 * HID + j] = Sx * w0;       // d/dx1
            S[2 * HID + j] = Sx * w1;       // d/dx2
            S[3 * HID + j] = Sx * w2;       // d/dt
            S[4 * HID + j] = c2 * w0 * w0;  // d2/dx1dx1 (z'' = 0 in layer 0)
            S[5 * HID + j] = c2 * w0 * w1;  // d2/dx1dx2
            S[6 * HID + j] = c2 * w1 * w1;  // d2/dx2dx2
        }
        __syncwarp();

        hidden_layer(S, W1T, b1, lane);
        hidden_layer(S, W2T, b2, lane);

        // ---- final linear layer (128 -> 3), all 7 channels ----
        float o0[7], o1[7], o2[7];
#pragma unroll
        for (int c = 0; c < 7; c++) { o0[c] = 0.f; o1[c] = 0.f; o2[c] = 0.f; }
#pragma unroll
        for (int u = 0; u < 4; u++) {
            int j = lane + 32 * u;
            float wa = W3[3 * j], wb = W3[3 * j + 1], wc = W3[3 * j + 2];
#pragma unroll
            for (int c = 0; c < 7; c++) {
                float sv = S[c * HID + j];
                o0[c] = fmaf(sv, wa, o0[c]);
                o1[c] = fmaf(sv, wb, o1[c]);
                o2[c] = fmaf(sv, wc, o2[c]);
            }
        }
        __syncwarp();   // done reading S (next point's layer 0 will overwrite)

#pragma unroll
        for (int c = 0; c < 7; c++) {
#pragma unroll
            for (int off = 16; off; off >>= 1) {
                o0[c] += __shfl_down_sync(0xffffffffu, o0[c], off);
                o1[c] += __shfl_down_sync(0xffffffffu, o1[c], off);
                o2[c] += __shfl_down_sync(0xffffffffu, o2[c], off);
            }
        }

        if (lane == 0) {
            // channel map: 0=v 1=dx1 2=dx2 3=dt 4=dx1x1 5=dx1x2 6=dx2x2
            float s0   = o0[0] + b3[0];
            float phi  = expf(-s0);
            float s0_1 = o0[1], s0_2 = o0[2], s0_t = o0[3];
            float s0_11 = o0[4], s0_22 = o0[6];

            float u1_1 = o1[1], u1_2 = o1[2];
            float u2_1 = o2[1], u2_2 = o2[2];
            float u1_11 = o1[4], u1_12 = o1[5], u1_22 = o1[6];
            float u2_11 = o2[4], u2_12 = o2[5], u2_22 = o2[6];

            // div(sigma)
            float div1 = (MU + LAM) * (u1_11 + u2_12) + MU * (u1_11 + u1_22);
            float div2 = (MU + LAM) * (u1_12 + u2_22) + MU * (u2_11 + u2_22);
            float om   = 1.f - phi;
            float g    = om * om;
            float res_stress = fabsf(g * div1) + fabsf(g * div2);

            // psi
            float tr  = u1_1 + u2_2;
            float trp = 0.5f * (tr + fabsf(tr));
            float pos = 0.5f * (LAM + MU) * trp * trp;
            float e12 = 0.5f * (u1_2 + u2_1);
            float d11 = u1_1 - 0.5f * tr;
            float d22 = u2_2 - 0.5f * tr;
            float psi = pos + MU * (d11 * d11 + d22 * d22 + 2.f * e12 * e12);

            // phase-field residual
            float lap = phi * (s0_1 * s0_1 + s0_2 * s0_2 - s0_11 - s0_22);
            float pf  = GC * (phi / LEN - LEN * lap) - 2.f * om * psi;

            // irreversibility: relu(-dphi/dt), dphi/dt = -phi * s0_t
            float irr = fmaxf(phi * s0_t, 0.f);

            a0 += (double)(res_stress * res_stress);
            a1 += (double)(pf * pf);
            a2 += (double)irr;
        }
    }

    if (lane == 0) {
        const int wg = blockIdx.x * WARPS_PER_BLOCK + warp;
        g_part[wg][0] = a0;
        g_part[wg][1] = a1;
        g_part[wg][2] = a2;
    }

    // ---- fused deterministic final reduction (last block done) ----
    __shared__ int is_last;
    __shared__ double red[WARPS_PER_BLOCK][3];
    __syncthreads();
    if (tid == 0) {
        __threadfence();
        int v = atomicAdd(&g_count, 1);
        is_last = (v == NBLOCKS - 1) ? 1 : 0;
    }
    __syncthreads();
    if (is_last) {
        __threadfence();   // acquire: make other blocks' partials visible
        double s[3] = {0.0, 0.0, 0.0};
        for (int i = tid; i < NWG; i += NTHREADS) {
            s[0] += g_part[i][0];
            s[1] += g_part[i][1];
            s[2] += g_part[i][2];
        }
#pragma unroll
        for (int c = 0; c < 3; c++)
#pragma unroll
            for (int off = 16; off; off >>= 1)
                s[c] += __shfl_down_sync(0xffffffffu, s[c], off);
        if (lane == 0) {
            red[warp][0] = s[0]; red[warp][1] = s[1]; red[warp][2] = s[2];
        }
        __syncthreads();
        if (warp == 0) {
            double v0 = (lane < WARPS_PER_BLOCK) ? red[lane][0] : 0.0;
            double v1 = (lane < WARPS_PER_BLOCK) ? red[lane][1] : 0.0;
            double v2 = (lane < WARPS_PER_BLOCK) ? red[lane][2] : 0.0;
#pragma unroll
            for (int off = 16; off; off >>= 1) {
                v0 += __shfl_down_sync(0xffffffffu, v0, off);
                v1 += __shfl_down_sync(0xffffffffu, v1, off);
                v2 += __shfl_down_sync(0xffffffffu, v2, off);
            }
            if (lane == 0) {
                out[0] = (float)(v0 / (double)NPTS);
                out[1] = (float)(v1 / (double)NPTS);
                out[2] = (float)(v2 / (double)NPTS);
                g_count = 0;   // reset for next (graph-replayed) launch
            }
        }
    }
}

extern "C" void kernel_launch(void* const* d_in, const int* in_sizes, int n_in,
                              void* d_out, int out_size)
{
    const float* x  = (const float*)d_in[0];
    const float* t  = (const float*)d_in[1];
    const float* W0 = (const float*)d_in[2];
    const float* b0 = (const float*)d_in[3];
    const float* W1 = (const float*)d_in[4];
    const float* b1 = (const float*)d_in[5];
    const float* W2 = (const float*)d_in[6];
    const float* b2 = (const float*)d_in[7];
    const float* W3 = (const float*)d_in[8];
    const float* b3 = (const float*)d_in[9];

    cudaFuncSetAttribute(pinn_kernel,
                         cudaFuncAttributeMaxDynamicSharedMemorySize, SMEM_BYTES);

    pinn_kernel<<<NBLOCKS, NTHREADS, SMEM_BYTES>>>(
        x, t, W0, b0, W1, b1, W2, b2, W3, b3, (float*)d_out);
}

// round 11
// speedup vs baseline: 1.9364x; 1.9364x over previous
#include <cuda_runtime.h>
#include <cuda_bf16.h>
#include <stdint.h>
#include <math.h>

#define NPTS 8192
#define NBLOCKS 148
#define NTHREADS 512
#define TILES 512

#define MU 80.77f
#define LAM 121.15f
#define GC 2.7e-3f
#define LEN 0.015f

// ---- SMEM byte offsets ----
#define SM_AHI   0        // A hi: 128 rows x 256B (bf16, swizzled)
#define SM_ALO   32768
#define SM_W1HI  65536    // W k-major [k][n] bf16, swizzled
#define SM_W1LO  98304
#define SM_W2HI  131072
#define SM_W2LO  163840
#define SM_STAGE 196608   // C stage: 32 cols x 132 floats = 16896 B
#define SM_W0P   213504   // float4[128]: (W0r0, W0r1, W0r2, b0)
#define SM_W3P   215552   // float4[128]: (W3[j][0..2], 0)
#define SM_B1    217600
#define SM_B2    218112
#define SM_PARTJ 218624   // float[16][24]
#define SMEM_TOTAL 220160

__device__ double g_part[NBLOCKS][3];
__device__ int g_count = 0;

__device__ __forceinline__ uint32_t smem_u32_of(const void* p) {
    uint32_t a;
    asm("{ .reg .u64 tmp; cvta.to.shared.u64 tmp, %1; cvt.u32.u64 %0, tmp; }"
        : "=r"(a) : "l"(p));
    return a;
}
__device__ __forceinline__ void ldsm4(uint32_t r[4], uint32_t addr) {
    asm volatile("ldmatrix.sync.aligned.m8n8.x4.shared.b16 {%0,%1,%2,%3}, [%4];"
                 : "=r"(r[0]), "=r"(r[1]), "=r"(r[2]), "=r"(r[3]) : "r"(addr));
}
__device__ __forceinline__ void ldsm4t(uint32_t r[4], uint32_t addr) {
    asm volatile("ldmatrix.sync.aligned.m8n8.x4.trans.shared.b16 {%0,%1,%2,%3}, [%4];"
                 : "=r"(r[0]), "=r"(r[1]), "=r"(r[2]), "=r"(r[3]) : "r"(addr));
}
__device__ __forceinline__ void mma16816(float c[4], const uint32_t a[4],
                                         uint32_t b0, uint32_t b1) {
    asm volatile(
        "mma.sync.aligned.m16n8k16.row.col.f32.bf16.bf16.f32 "
        "{%0,%1,%2,%3}, {%4,%5,%6,%7}, {%8,%9}, {%0,%1,%2,%3};"
        : "+f"(c[0]), "+f"(c[1]), "+f"(c[2]), "+f"(c[3])
        : "r"(a[0]), "r"(a[1]), "r"(a[2]), "r"(a[3]), "r"(b0), "r"(b1));
}

// write one activation value into A hi/lo (bf16 split, swizzled)
__device__ __forceinline__ void writeA_pair(char* smem, int row, int jj, float v) {
    uint32_t off = (uint32_t)row * 256u
                 + ((((uint32_t)(jj >> 3) ^ ((uint32_t)row & 15u)) << 4)
                 | (((uint32_t)jj & 7u) << 1));
    __nv_bfloat16 h = __float2bfloat16(v);
    *(__nv_bfloat16*)(smem + SM_AHI + off) = h;
    *(__nv_bfloat16*)(smem + SM_ALO + off) = __float2bfloat16(v - __bfloat162float(h));
}

// 128x128x128 bf16 3-term split GEMM; acc = per-warp C fragments
__device__ __forceinline__ void gemm_layer(uint32_t su, int rb, int cg, int lane,
                                           uint32_t whi_off, float acc[4][2][4]) {
#pragma unroll
    for (int nb = 0; nb < 4; nb++)
#pragma unroll
        for (int h = 0; h < 2; h++)
#pragma unroll
            for (int e = 0; e < 4; e++) acc[nb][h][e] = 0.f;

    const int m = lane >> 3;
    const int row_a = rb * 16 + (lane & 7) + ((m & 1) << 3);
    const int krow_l = (lane & 7) + ((m & 1) << 3);
#pragma unroll
    for (int k = 0; k < 8; k++) {
        uint32_t ua = (uint32_t)((k * 2 + (m >> 1)) ^ (row_a & 15));
        uint32_t aaddr = su + SM_AHI + (uint32_t)row_a * 256u + ua * 16u;
        uint32_t ahi[4], alo[4];
        ldsm4(ahi, aaddr);
        ldsm4(alo, aaddr + 32768u);
#pragma unroll
        for (int nb = 0; nb < 4; nb++) {
            int ncol = cg * 64 + nb * 16;
            int krow = k * 16 + krow_l;
            uint32_t un = (uint32_t)((((ncol >> 3) + (m >> 1))) ^ (krow & 15));
            uint32_t baddr = su + whi_off + (uint32_t)krow * 256u + un * 16u;
            uint32_t bhi[4], blo[4];
            ldsm4t(bhi, baddr);
            ldsm4t(blo, baddr + 32768u);
#pragma unroll
            for (int h = 0; h < 2; h++) {
                mma16816(acc[nb][h], ahi, bhi[2 * h], bhi[2 * h + 1]);
                mma16816(acc[nb][h], ahi, blo[2 * h], blo[2 * h + 1]);
                mma16816(acc[nb][h], alo, bhi[2 * h], bhi[2 * h + 1]);
            }
        }
    }
}

// stage this warp's C fragments for 32-col chunk ch into SM_STAGE [col][row]
__device__ __forceinline__ void stage_chunk(char* smem, int ch, int rb, int cg,
                                            int lane, float acc[4][2][4]) {
    if (cg != (ch >> 1)) return;
    float* st = (float*)(smem + SM_STAGE);
    const int g = lane >> 2, tig = lane & 3;
#pragma unroll
    for (int tl = 0; tl < 2; tl++) {
        int tt = 2 * (ch & 1) + tl;
#pragma unroll
        for (int h = 0; h < 2; h++) {
            int jc = tl * 16 + h * 8 + 2 * tig;
            int base = jc * 132 + rb * 16 + g;
            st[base]           = acc[tt][h][0];
            st[base + 132]     = acc[tt][h][1];
            st[base + 8]       = acc[tt][h][2];
            st[base + 132 + 8] = acc[tt][h][3];
        }
    }
}

// activation epilogue for chunk ch; LAYER=1 writes next A, LAYER=2 folds W3
template <int LAYER>
__device__ __forceinline__ void epi_chunk(char* smem, int ch, int tid, float* Jacc) {
    const int l = tid & 31, p = tid >> 5;
    const int jj = ch * 32 + l;
    const float* st = (const float*)(smem + SM_STAGE);
    float zs[8];
    *(float4*)zs       = *(const float4*)(st + l * 132 + p * 8);
    *(float4*)(zs + 4) = *(const float4*)(st + l * 132 + p * 8 + 4);
    const float bjj = ((const float*)(smem + (LAYER == 1 ? SM_B1 : SM_B2)))[jj];
    float z = zs[0] + bjj;
    float T = tanhf(z);
    float Sx = 1.f - T * T;
    float c2 = -2.f * T * Sx;
    float o[8];
    o[0] = T; o[1] = Sx * zs[1]; o[2] = Sx * zs[2]; o[3] = Sx * zs[3];
    o[4] = fmaf(c2 * zs[1], zs[1], Sx * zs[4]);
    o[5] = fmaf(c2 * zs[1], zs[2], Sx * zs[5]);
    o[6] = fmaf(c2 * zs[2], zs[2], Sx * zs[6]);
    o[7] = 0.f;
    if (LAYER == 1) {
#pragma unroll
        for (int c = 0; c < 8; c++) writeA_pair(smem, p * 8 + c, jj, o[c]);
    } else {
        float4 w3 = ((const float4*)(smem + SM_W3P))[jj];
#pragma unroll
        for (int c = 0; c < 7; c++) {
            Jacc[c * 3 + 0] = fmaf(o[c], w3.x, Jacc[c * 3 + 0]);
            Jacc[c * 3 + 1] = fmaf(o[c], w3.y, Jacc[c * 3 + 1]);
            Jacc[c * 3 + 2] = fmaf(o[c], w3.z, Jacc[c * 3 + 2]);
        }
    }
}

__global__ __launch_bounds__(NTHREADS, 1)
void pinn_kernel(const float* __restrict__ x,  const float* __restrict__ t,
                 const float* __restrict__ W0, const float* __restrict__ b0,
                 const float* __restrict__ W1, const float* __restrict__ b1,
                 const float* __restrict__ W2, const float* __restrict__ b2,
                 const float* __restrict__ W3, const float* __restrict__ b3,
                 float* __restrict__ out)
{
    extern __shared__ char smem[];
    const uint32_t su = smem_u32_of(smem);
    const int tid = threadIdx.x, warp = tid >> 5, lane = tid & 31;
    const int rb = warp & 7, cg = warp >> 3;

    // ---- init: weights (k-major, bf16 hi/lo, swizzled), vectors ----
    for (int idx = tid; idx < 16384; idx += NTHREADS) {
        int k = idx >> 7, n = idx & 127;
        uint32_t off = (uint32_t)k * 256u
                     + ((((uint32_t)(n >> 3) ^ ((uint32_t)k & 15u)) << 4)
                     | (((uint32_t)n & 7u) << 1));
        float w = W1[idx];
        __nv_bfloat16 h = __float2bfloat16(w);
        *(__nv_bfloat16*)(smem + SM_W1HI + off) = h;
        *(__nv_bfloat16*)(smem + SM_W1LO + off) = __float2bfloat16(w - __bfloat162float(h));
        w = W2[idx];
        h = __float2bfloat16(w);
        *(__nv_bfloat16*)(smem + SM_W2HI + off) = h;
        *(__nv_bfloat16*)(smem + SM_W2LO + off) = __float2bfloat16(w - __bfloat162float(h));
    }
    for (int j = tid; j < 128; j += NTHREADS) {
        ((float4*)(smem + SM_W0P))[j] = make_float4(W0[j], W0[128 + j], W0[256 + j], b0[j]);
        ((float4*)(smem + SM_W3P))[j] = make_float4(W3[3 * j], W3[3 * j + 1], W3[3 * j + 2], 0.f);
        ((float*)(smem + SM_B1))[j] = b1[j];
        ((float*)(smem + SM_B2))[j] = b2[j];
    }
    __syncthreads();

    const int t0 = (blockIdx.x * TILES) / NBLOCKS;
    const int t1 = ((blockIdx.x + 1) * TILES) / NBLOCKS;
    double a0 = 0.0, a1 = 0.0, a2 = 0.0;
    const float b3v = b3[0];
    float acc[4][2][4];

    for (int tile = t0; tile < t1; tile++) {
        // ---- layer-0 analytic jet seed -> A ----
#pragma unroll
        for (int it = 0; it < 4; it++) {
            int jj = tid & 127;
            int p = (tid >> 7) + it * 4;
            int gp = tile * 16 + p;
            float x1 = x[2 * gp], x2 = x[2 * gp + 1], ttv = t[gp];
            float4 w = ((const float4*)(smem + SM_W0P))[jj];
            float z = fmaf(ttv, w.z, fmaf(x2, w.y, fmaf(x1, w.x, w.w)));
            float T = tanhf(z);
            float Sx = 1.f - T * T;
            float c2 = -2.f * T * Sx;
            float o[8] = {T, Sx * w.x, Sx * w.y, Sx * w.z,
                          c2 * w.x * w.x, c2 * w.x * w.y, c2 * w.y * w.y, 0.f};
#pragma unroll
            for (int c = 0; c < 8; c++) writeA_pair(smem, p * 8 + c, jj, o[c]);
        }
        __syncthreads();

        // ---- hidden layer 1 ----
        gemm_layer(su, rb, cg, lane, SM_W1HI, acc);
        __syncthreads();
        for (int ch = 0; ch < 4; ch++) {
            stage_chunk(smem, ch, rb, cg, lane, acc);
            __syncthreads();
            epi_chunk<1>(smem, ch, tid, (float*)0);
            __syncthreads();
        }

        // ---- hidden layer 2 + W3 fold ----
        gemm_layer(su, rb, cg, lane, SM_W2HI, acc);
        __syncthreads();
        float Jacc[21];
#pragma unroll
        for (int c = 0; c < 21; c++) Jacc[c] = 0.f;
        for (int ch = 0; ch < 4; ch++) {
            stage_chunk(smem, ch, rb, cg, lane, acc);
            __syncthreads();
            epi_chunk<2>(smem, ch, tid, Jacc);
            __syncthreads();
        }
#pragma unroll
        for (int c = 0; c < 21; c++) {
#pragma unroll
            for (int off = 16; off; off >>= 1)
                Jacc[c] += __shfl_down_sync(0xffffffffu, Jacc[c], off);
        }
        if (lane == 0) {
            float* PJ = (float*)(smem + SM_PARTJ);
#pragma unroll
            for (int c = 0; c < 21; c++) PJ[warp * 24 + c] = Jacc[c];
        }
        __syncthreads();

        // ---- physics residuals (warp 0, one lane per point) ----
        if (warp == 0 && lane < 16) {
            const float* PJ = (const float*)(smem + SM_PARTJ) + lane * 24;
            float J0[7], J1[7], J2[7];
#pragma unroll
            for (int c = 0; c < 7; c++) {
                J0[c] = PJ[c * 3 + 0]; J1[c] = PJ[c * 3 + 1]; J2[c] = PJ[c * 3 + 2];
            }
            float s0v = J0[0] + b3v;
            float phi = expf(-s0v);
            float div1 = (MU + LAM) * (J1[4] + J2[5]) + MU * (J1[4] + J1[6]);
            float div2 = (MU + LAM) * (J1[5] + J2[6]) + MU * (J2[4] + J2[6]);
            float om = 1.f - phi, g = om * om;
            float res_stress = fabsf(g * div1) + fabsf(g * div2);
            float tr = J1[1] + J2[2];
            float trp = 0.5f * (tr + fabsf(tr));
            float pos = 0.5f * (LAM + MU) * trp * trp;
            float e12 = 0.5f * (J1[2] + J2[1]);
            float d11 = J1[1] - 0.5f * tr;
            float d22 = J2[2] - 0.5f * tr;
            float psi = pos + MU * (d11 * d11 + d22 * d22 + 2.f * e12 * e12);
            float lap = phi * (J0[1] * J0[1] + J0[2] * J0[2] - J0[4] - J0[6]);
            float pf = GC * (phi / LEN - LEN * lap) - 2.f * om * psi;
            float irr = fmaxf(phi * J0[3], 0.f);
            a0 += (double)(res_stress * res_stress);
            a1 += (double)(pf * pf);
            a2 += (double)irr;
        }
        __syncthreads();
    }

    if (warp == 0) {
#pragma unroll
        for (int off = 8; off; off >>= 1) {
            a0 += __shfl_down_sync(0xffffffffu, a0, off);
            a1 += __shfl_down_sync(0xffffffffu, a1, off);
            a2 += __shfl_down_sync(0xffffffffu, a2, off);
        }
        if (lane == 0) {
            g_part[blockIdx.x][0] = a0;
            g_part[blockIdx.x][1] = a1;
            g_part[blockIdx.x][2] = a2;
        }
    }

    __shared__ int is_last;
    __syncthreads();
    if (tid == 0) {
        __threadfence();
        is_last = (atomicAdd(&g_count, 1) == NBLOCKS - 1) ? 1 : 0;
    }
    __syncthreads();
    if (is_last && warp == 0) {
        __threadfence();
        double s0 = 0.0, s1 = 0.0, s2 = 0.0;
        for (int i = lane; i < NBLOCKS; i += 32) {
            s0 += g_part[i][0]; s1 += g_part[i][1]; s2 += g_part[i][2];
        }
#pragma unroll
        for (int off = 16; off; off >>= 1) {
            s0 += __shfl_down_sync(0xffffffffu, s0, off);
            s1 += __shfl_down_sync(0xffffffffu, s1, off);
            s2 += __shfl_down_sync(0xffffffffu, s2, off);
        }
        if (lane == 0) {
            out[0] = (float)(s0 / (double)NPTS);
            out[1] = (float)(s1 / (double)NPTS);
            out[2] = (float)(s2 / (double)NPTS);
            g_count = 0;
        }
    }
}

extern "C" void kernel_launch(void* const* d_in, const int* in_sizes, int n_in,
                              void* d_out, int out_size)
{
    const float* x  = (const float*)d_in[0];
    const float* t  = (const float*)d_in[1];
    const float* W0 = (const float*)d_in[2];
    const float* b0 = (const float*)d_in[3];
    const float* W1 = (const float*)d_in[4];
    const float* b1 = (const float*)d_in[5];
    const float* W2 = (const float*)d_in[6];
    const float* b2 = (const float*)d_in[7];
    const float* W3 = (const float*)d_in[8];
    const float* b3 = (const float*)d_in[9];

    cudaFuncSetAttribute(pinn_kernel,
                         cudaFuncAttributeMaxDynamicSharedMemorySize, SMEM_TOTAL);
    pinn_kernel<<<NBLOCKS, NTHREADS, SMEM_TOTAL>>>(
        x, t, W0, b0, W1, b1, W2, b2, W3, b3, (float*)d_out);
}